// round 15
// baseline (speedup 1.0000x reference)
#include <cuda_runtime.h>
#include <math.h>

#define Bc 2
#define Sc 2048
#define Tc 8
#define Cc 128
#define Kc 16
#define Hc 4
#define Fc 130        // C+2
#define Nc 32768
#define Uc 520        // H*(C+2)
#define UP 528        // padded row stride for U/NB
#define NBS 140       // nb row stride (conflict-free for frag loads)

typedef unsigned int u32;

// ---- scratch (__device__ globals; no allocations allowed) ----
__device__ float g_Wu[Cc*UP];             // [c][j] tf32 bits, pad j>=520 zero
__device__ float g_WoT[UP*Cc];            // [j][c'] tf32 bits, pad rows zero
__device__ float g_U[(size_t)Nc*UP];      // fp32
__device__ float g_NB[(size_t)Nc*UP];     // tf32 bits (written by k2)
__device__ int   g_is64;

__device__ __forceinline__ u32 tf32_of(float f) {
    u32 u;
    asm("cvt.rna.tf32.f32 %0, %1;" : "=r"(u) : "f"(f));
    return u;
}
__device__ __forceinline__ void mma_tf32(float* d, u32 a0, u32 a1, u32 a2, u32 a3,
                                         u32 b0, u32 b1) {
    asm("mma.sync.aligned.m16n8k8.row.col.f32.tf32.tf32.f32 "
        "{%0,%1,%2,%3}, {%4,%5,%6,%7}, {%8,%9}, {%0,%1,%2,%3};"
        : "+f"(d[0]), "+f"(d[1]), "+f"(d[2]), "+f"(d[3])
        : "r"(a0), "r"(a1), "r"(a2), "r"(a3), "r"(b0), "r"(b1));
}

// ---------------------------------------------------------------------------
// k0: combined weights (tf32, zero-padded) + int32/int64 index sniff (block 0).
// ---------------------------------------------------------------------------
__global__ void k0_combine(const float* __restrict__ Wq, const float* __restrict__ Wk,
                           const float* __restrict__ Wv, const float* __restrict__ Wp,
                           const unsigned int* __restrict__ sp) {
    __shared__ int any;
    if (blockIdx.x == 0) {
        if (threadIdx.x == 0) any = 0;
        __syncthreads();
        for (int i = threadIdx.x; i < 4096; i += blockDim.x)
            if (sp[2*i + 1] != 0u) any = 1;
        __syncthreads();
        if (threadIdx.x == 0) g_is64 = (any == 0) ? 1 : 0;
    }

    int i = blockIdx.x * blockDim.x + threadIdx.x;
    if (i >= Cc*UP) return;
    int c = i / UP;
    int j = i % UP;
    float su = 0.f, so = 0.f;
    if (j < Uc) {
        int h = j / Fc;
        int f = j % Fc;
        #pragma unroll
        for (int d = 0; d < 32; d++) {
            int hd = h*32 + d;
            su = fmaf(Wq[hd*Cc + c], Wk[hd*(Cc+2) + f], su);
            so = fmaf(Wp[c*Cc + hd], Wv[hd*(Cc+2) + f], so);
        }
        su *= rsqrtf(32.f);
    }
    g_Wu[c*UP + j]  = __uint_as_float(tf32_of(su));
    g_WoT[j*Cc + c] = __uint_as_float(tf32_of(so));
}

// ---------------------------------------------------------------------------
// k1: U = X_ @ W_u via tf32 MMA (R8 verbatim).
// ---------------------------------------------------------------------------
__global__ __launch_bounds__(256) void k1_u(const float* __restrict__ x) {
    extern __shared__ u32 sm1[];
    u32* xs = sm1;                 // 128*132
    u32* ws = sm1 + 128*132;       // 128*72
    int base = blockIdx.x * 128;
    int bt = base >> 11;
    int s0 = base & 2047;
    int b = bt >> 3, t = bt & 7;
    int tid = threadIdx.x;
    int wid = tid >> 5, lane = tid & 31, gid = lane >> 2, tig = lane & 3;
    int m0 = wid * 16;

    for (int idx = tid; idx < 4096; idx += 256) {
        int r = idx >> 5, c4 = idx & 31;
        float4 v = ((const float4*)(x + ((size_t)((b*Sc + s0 + r)*Tc + t))*Cc))[c4];
        uint4 u = make_uint4(tf32_of(v.x), tf32_of(v.y), tf32_of(v.z), tf32_of(v.w));
        *((uint4*)&xs[r*132 + c4*4]) = u;
    }
    __syncthreads();

    int rowA0 = (m0 + gid) * 132;
    int rowA1 = (m0 + gid + 8) * 132;

    for (int ch = 0; ch < 9; ch++) {
        int j0 = ch * 64;
        int jtn = (ch < 8) ? 8 : 2;
        int jw4 = jtn * 2;
        if (ch) __syncthreads();
        for (int idx = tid; idx < 128*jw4; idx += 256) {
            int c = idx / jw4, q = idx - c*jw4;
            uint4 w = ((const uint4*)(g_Wu + (size_t)c*UP + j0))[q];
            *((uint4*)&ws[c*72 + q*4]) = w;
        }
        __syncthreads();

        float acc[8][4];
        #pragma unroll
        for (int jt = 0; jt < 8; jt++)
            #pragma unroll
            for (int e = 0; e < 4; e++) acc[jt][e] = 0.f;

        #pragma unroll
        for (int ks = 0; ks < 16; ks++) {
            int kk = ks * 8;
            u32 a0 = xs[rowA0 + kk + tig];
            u32 a1 = xs[rowA1 + kk + tig];
            u32 a2 = xs[rowA0 + kk + tig + 4];
            u32 a3 = xs[rowA1 + kk + tig + 4];
            const u32* w0p = &ws[(kk + tig)*72 + gid];
            const u32* w1p = &ws[(kk + tig + 4)*72 + gid];
            #pragma unroll
            for (int jt = 0; jt < 8; jt++) {
                if (jt < jtn) {
                    mma_tf32(acc[jt], a0, a1, a2, a3, w0p[jt*8], w1p[jt*8]);
                }
            }
        }
        #pragma unroll
        for (int jt = 0; jt < 8; jt++) {
            if (jt < jtn) {
                int j = j0 + jt*8 + 2*tig;
                *((float2*)(g_U + (size_t)(base + m0 + gid    )*UP + j)) =
                    make_float2(acc[jt][0], acc[jt][1]);
                *((float2*)(g_U + (size_t)(base + m0 + gid + 8)*UP + j)) =
                    make_float2(acc[jt][2], acc[jt][3]);
            }
        }
    }
}

// ---------------------------------------------------------------------------
// k2: warp-autonomous attention (R11 winner, exact).
// ---------------------------------------------------------------------------
__global__ __launch_bounds__(128, 5) void k2_attn(const float* __restrict__ x,
                                                  const void* __restrict__ sidx,
                                                  const float* __restrict__ swgt,
                                                  const float* __restrict__ ali,
                                                  const float* __restrict__ dstp) {
    __shared__ __align__(16) float nb[4][Kc][NBS];     // 35.8 KB
    __shared__ __align__(16) float attn_s[4][Kc][4];   // [k][h] fp32
    __shared__ float logw[4][Kc];

    int tid = threadIdx.x;
    int n4 = tid >> 5, lane = tid & 31;
    int n = blockIdx.x * 4 + n4;
    int bt = n >> 11;
    int b = bt >> 3, t = bt & 7;
    int k = lane & 15, half = lane >> 4;
    int gid = lane >> 2, tig = lane & 3;

    // ---- P0: neighbor index (one per k, lanes 0-15 authoritative) ----
    int myjn;
    if (g_is64) myjn = (int)((const long long*)sidx)[(size_t)n*Kc + k];
    else        myjn = ((const int*)sidx)[(size_t)n*Kc + k];

    // coalesced gather: kg = lane>>3 (4 rows per pass), l8 = lane&7
    {
        int kg = lane >> 3, l8 = lane & 7;
        size_t xbase = ((size_t)(b*Sc))*Tc*Cc + (size_t)t*Cc;
        #pragma unroll
        for (int set = 0; set < 4; set++) {
            int kk = set*4 + kg;
            int jn_kk = __shfl_sync(0xffffffffu, myjn, kk);
            const float4* srck = (const float4*)(x + xbase + (size_t)jn_kk*Tc*Cc);
            #pragma unroll
            for (int q = 0; q < 4; q++) {
                int f4 = l8 + 8*q;
                *((float4*)&nb[n4][kk][f4*4]) = srck[f4];
            }
        }
    }
    if (half == 0) {
        nb[n4][k][128] = ali [(size_t)n*Kc + k];
        nb[n4][k][129] = dstp[(size_t)n*Kc + k];
    } else {
        #pragma unroll
        for (int e = 0; e < 6; e++) nb[n4][k][130 + e] = 0.f;  // zero MMA pad
    }
    if (lane < Kc)
        logw[n4][lane] = __logf(swgt[(size_t)n*Kc + lane] + 1e-6f);
    __syncwarp();

    // ---- P1: logits via 17 m16n8k8 tf32 MMAs; B direct from g_U ----
    float d[4] = {0.f, 0.f, 0.f, 0.f};
    {
        const float* nbr0 = &nb[n4][gid    ][0];
        const float* nbr1 = &nb[n4][gid + 8][0];
        const float* Urow = g_U + (size_t)n*UP + gid*Fc;   // only gid<4 read
        bool hv = (gid < 4);
        #pragma unroll
        for (int ks = 0; ks < 17; ks++) {
            int kk = ks * 8;
            u32 a0 = tf32_of(nbr0[kk + tig]);
            u32 a1 = tf32_of(nbr1[kk + tig]);
            u32 a2 = tf32_of(nbr0[kk + tig + 4]);
            u32 a3 = tf32_of(nbr1[kk + tig + 4]);
            int f0 = kk + tig, f1 = f0 + 4;
            u32 b0 = (hv && f0 < Fc) ? tf32_of(Urow[f0]) : 0u;
            u32 b1 = (hv && f1 < Fc) ? tf32_of(Urow[f1]) : 0u;
            mma_tf32(d, a0, a1, a2, a3, b0, b1);
        }
    }
    {
        float lw0 = logw[n4][gid];
        float lw1 = logw[n4][gid + 8];
        d[0] += lw0; d[1] += lw0;
        d[2] += lw1; d[3] += lw1;
    }

    // ---- P2: softmax over k (reduce over gid lanes: xor 4,8,16) ----
    {
        float m0 = fmaxf(d[0], d[2]);
        #pragma unroll
        for (int o = 4; o <= 16; o <<= 1)
            m0 = fmaxf(m0, __shfl_xor_sync(0xffffffffu, m0, o));
        float e0 = __expf(d[0] - m0), e2 = __expf(d[2] - m0);
        float s0 = e0 + e2;
        #pragma unroll
        for (int o = 4; o <= 16; o <<= 1)
            s0 += __shfl_xor_sync(0xffffffffu, s0, o);
        float a0 = e0 / s0, a2 = e2 / s0;

        float m1 = fmaxf(d[1], d[3]);
        #pragma unroll
        for (int o = 4; o <= 16; o <<= 1)
            m1 = fmaxf(m1, __shfl_xor_sync(0xffffffffu, m1, o));
        float e1 = __expf(d[1] - m1), e3 = __expf(d[3] - m1);
        float s1 = e1 + e3;
        #pragma unroll
        for (int o = 4; o <= 16; o <<= 1)
            s1 += __shfl_xor_sync(0xffffffffu, s1, o);
        float a1 = e1 / s1, a3 = e3 / s1;

        if (tig < 2) {   // heads 0..3 live in tig 0,1
            attn_s[n4][gid    ][2*tig    ] = a0;
            attn_s[n4][gid    ][2*tig + 1] = a1;
            attn_s[n4][gid + 8][2*tig    ] = a2;
            attn_s[n4][gid + 8][2*tig + 1] = a3;
        }
    }
    __syncwarp();

    // ---- P3: nbar; lane = f0, scalar fp32, attn via broadcast LDS.128 ----
    {
        float4 acc[4];
        float4 acc4t = make_float4(0.f,0.f,0.f,0.f);
        #pragma unroll
        for (int q = 0; q < 4; q++) acc[q] = make_float4(0.f,0.f,0.f,0.f);
        #pragma unroll
        for (int kk = 0; kk < Kc; kk++) {
            float4 a = *((const float4*)&attn_s[n4][kk][0]);
            const float* nbr = &nb[n4][kk][0];
            #pragma unroll
            for (int q = 0; q < 4; q++) {
                float v = nbr[lane + 32*q];
                acc[q].x = fmaf(a.x, v, acc[q].x);
                acc[q].y = fmaf(a.y, v, acc[q].y);
                acc[q].z = fmaf(a.z, v, acc[q].z);
                acc[q].w = fmaf(a.w, v, acc[q].w);
            }
            if (lane < 2) {
                float v = nbr[128 + lane];
                acc4t.x = fmaf(a.x, v, acc4t.x);
                acc4t.y = fmaf(a.y, v, acc4t.y);
                acc4t.z = fmaf(a.z, v, acc4t.z);
                acc4t.w = fmaf(a.w, v, acc4t.w);
            }
        }
        u32* dst = (u32*)(g_NB + (size_t)n*UP);
        #pragma unroll
        for (int q = 0; q < 4; q++) {
            int f = lane + 32*q;
            dst[0*Fc + f] = tf32_of(acc[q].x);
            dst[1*Fc + f] = tf32_of(acc[q].y);
            dst[2*Fc + f] = tf32_of(acc[q].z);
            dst[3*Fc + f] = tf32_of(acc[q].w);
        }
        if (lane < 2) {
            int f = 128 + lane;
            dst[0*Fc + f] = tf32_of(acc4t.x);
            dst[1*Fc + f] = tf32_of(acc4t.y);
            dst[2*Fc + f] = tf32_of(acc4t.z);
            dst[3*Fc + f] = tf32_of(acc4t.w);
        }
        if (lane < 8) dst[Uc + lane] = 0u;   // zero pad cols
    }
}

// ---------------------------------------------------------------------------
// k3: OUT = NB @ W_oT + bp via tf32 MMA. Retiled: 64 rows/block (grid 512),
// 8 warps = 4 m-strips x 2 n-halves (8 jt each, acc 32 regs). smem 73.5 KB
// => 3 blocks/SM (was 2); staging latency hidden by co-resident blocks.
// ---------------------------------------------------------------------------
__global__ __launch_bounds__(256, 3) void k3_out(const float* __restrict__ bp,
                                                 float* __restrict__ out) {
    extern __shared__ u32 sm3[];
    u32* as3 = sm3;                // 64*100 = 6400 words (25.6 KB)
    u32* ws3 = sm3 + 6400;         // 88*136 = 11968 words (47.9 KB)
    int base = blockIdx.x * 64;
    int bt = base >> 11;
    int s0 = base & 2047;
    int b = bt >> 3, t = bt & 7;
    int tid = threadIdx.x;
    int wid = tid >> 5, lane = tid & 31, gid = lane >> 2, tig = lane & 3;
    int mstrip = wid & 3, nh = wid >> 2;    // 4 m-strips x 2 n-halves
    int m0 = mstrip * 16;
    int rowA0 = (m0 + gid) * 100;
    int rowA1 = (m0 + gid + 8) * 100;

    float acc[8][4];
    #pragma unroll
    for (int jt = 0; jt < 8; jt++)
        #pragma unroll
        for (int e = 0; e < 4; e++) acc[jt][e] = 0.f;

    for (int ch = 0; ch < 6; ch++) {
        if (ch) __syncthreads();
        // stage NB chunk: 64 rows x 22 uint4
        for (int idx = tid; idx < 64*22; idx += 256) {
            int r = idx / 22, q = idx - r*22;
            uint4 v = ((const uint4*)(g_NB + (size_t)(base + r)*UP + ch*88))[q];
            *((uint4*)&as3[r*100 + q*4]) = v;
        }
        // stage WoT chunk: 88 rows x 32 uint4
        for (int idx = tid; idx < 88*32; idx += 256) {
            int kk = idx >> 5, q = idx & 31;
            uint4 w = ((const uint4*)(g_WoT + (size_t)(ch*88 + kk)*Cc))[q];
            *((uint4*)&ws3[kk*136 + q*4]) = w;
        }
        __syncthreads();

        #pragma unroll
        for (int ks = 0; ks < 11; ks++) {
            int kk = ks * 8;
            u32 a0 = as3[rowA0 + kk + tig];
            u32 a1 = as3[rowA1 + kk + tig];
            u32 a2 = as3[rowA0 + kk + tig + 4];
            u32 a3 = as3[rowA1 + kk + tig + 4];
            const u32* w0p = &ws3[(kk + tig)*136 + nh*64 + gid];
            const u32* w1p = &ws3[(kk + tig + 4)*136 + nh*64 + gid];
            #pragma unroll
            for (int jt = 0; jt < 8; jt++)
                mma_tf32(acc[jt], a0, a1, a2, a3, w0p[jt*8], w1p[jt*8]);
        }
    }

    #pragma unroll
    for (int jt = 0; jt < 8; jt++) {
        int cp = nh*64 + jt*8 + 2*tig;
        float2 bv = *((const float2*)&bp[cp]);
        int sA = s0 + m0 + gid;
        int sB = sA + 8;
        *((float2*)(out + ((size_t)((b*Sc + sA)*Tc + t))*Cc + cp)) =
            make_float2(acc[jt][0] + bv.x, acc[jt][1] + bv.y);
        *((float2*)(out + ((size_t)((b*Sc + sB)*Tc + t))*Cc + cp)) =
            make_float2(acc[jt][2] + bv.x, acc[jt][3] + bv.y);
    }
}

// ---------------------------------------------------------------------------
extern "C" void kernel_launch(void* const* d_in, const int* in_sizes, int n_in,
                              void* d_out, int out_size) {
    const float* x    = (const float*)d_in[0];
    const void*  sidx = d_in[1];
    const float* swgt = (const float*)d_in[2];
    const float* ali  = (const float*)d_in[3];
    const float* dstp = (const float*)d_in[4];
    const float* Wq   = (const float*)d_in[5];
    const float* Wk   = (const float*)d_in[6];
    const float* Wv   = (const float*)d_in[7];
    const float* Wp   = (const float*)d_in[8];
    const float* bp   = (const float*)d_in[9];
    float* out = (float*)d_out;

    const int SM1 = (128*132 + 128*72) * 4;
    const int SM3 = (6400 + 11968) * 4;      // 73,472 B
    cudaFuncSetAttribute(k1_u,   cudaFuncAttributeMaxDynamicSharedMemorySize, SM1);
    cudaFuncSetAttribute(k3_out, cudaFuncAttributeMaxDynamicSharedMemorySize, SM3);

    k0_combine<<<(Cc*UP + 255)/256, 256>>>(Wq, Wk, Wv, Wp,
                                           (const unsigned int*)sidx);
    k1_u<<<Nc/128, 256, SM1>>>(x);
    k2_attn<<<Nc/4, 128>>>(x, sidx, swgt, ali, dstp);
    k3_out<<<Nc/64, 256, SM3>>>(bp, out);
}

// round 16
// speedup vs baseline: 1.2019x; 1.2019x over previous
#include <cuda_runtime.h>
#include <math.h>

#define Bc 2
#define Sc 2048
#define Tc 8
#define Cc 128
#define Kc 16
#define Hc 4
#define Fc 130        // C+2
#define Nc 32768
#define Uc 520        // H*(C+2)
#define UP 528        // padded row stride for U/NB
#define NBS 140       // nb row stride (conflict-free for frag loads)

typedef unsigned int u32;

// ---- scratch (__device__ globals; no allocations allowed) ----
__device__ float g_Wu[Cc*UP];             // [c][j] tf32 bits, pad j>=520 zero
__device__ float g_WoT[UP*Cc];            // [j][c'] tf32 bits, pad rows zero
__device__ float g_U[(size_t)Nc*UP];      // fp32
__device__ float g_NB[(size_t)Nc*UP];     // tf32 bits (written by k2)
__device__ int   g_is64;

__device__ __forceinline__ u32 tf32_of(float f) {
    u32 u;
    asm("cvt.rna.tf32.f32 %0, %1;" : "=r"(u) : "f"(f));
    return u;
}
__device__ __forceinline__ void mma_tf32(float* d, u32 a0, u32 a1, u32 a2, u32 a3,
                                         u32 b0, u32 b1) {
    asm("mma.sync.aligned.m16n8k8.row.col.f32.tf32.tf32.f32 "
        "{%0,%1,%2,%3}, {%4,%5,%6,%7}, {%8,%9}, {%0,%1,%2,%3};"
        : "+f"(d[0]), "+f"(d[1]), "+f"(d[2]), "+f"(d[3])
        : "r"(a0), "r"(a1), "r"(a2), "r"(a3), "r"(b0), "r"(b1));
}
__device__ __forceinline__ u32 smem_u32(const void* p) {
    u32 a;
    asm("{ .reg .u64 t; cvta.to.shared.u64 t, %1; cvt.u32.u64 %0, t; }"
        : "=r"(a) : "l"(p));
    return a;
}
__device__ __forceinline__ void cp16(u32 dst, const void* src) {
    asm volatile("cp.async.cg.shared.global [%0], [%1], 16;" :: "r"(dst), "l"(src));
}

// ---------------------------------------------------------------------------
// k0: combined weights (tf32, zero-padded) + int32/int64 index sniff (block 0).
// ---------------------------------------------------------------------------
__global__ void k0_combine(const float* __restrict__ Wq, const float* __restrict__ Wk,
                           const float* __restrict__ Wv, const float* __restrict__ Wp,
                           const unsigned int* __restrict__ sp) {
    __shared__ int any;
    if (blockIdx.x == 0) {
        if (threadIdx.x == 0) any = 0;
        __syncthreads();
        for (int i = threadIdx.x; i < 4096; i += blockDim.x)
            if (sp[2*i + 1] != 0u) any = 1;
        __syncthreads();
        if (threadIdx.x == 0) g_is64 = (any == 0) ? 1 : 0;
    }

    int i = blockIdx.x * blockDim.x + threadIdx.x;
    if (i >= Cc*UP) return;
    int c = i / UP;
    int j = i % UP;
    float su = 0.f, so = 0.f;
    if (j < Uc) {
        int h = j / Fc;
        int f = j % Fc;
        #pragma unroll
        for (int d = 0; d < 32; d++) {
            int hd = h*32 + d;
            su = fmaf(Wq[hd*Cc + c], Wk[hd*(Cc+2) + f], su);
            so = fmaf(Wp[c*Cc + hd], Wv[hd*(Cc+2) + f], so);
        }
        su *= rsqrtf(32.f);
    }
    g_Wu[c*UP + j]  = __uint_as_float(tf32_of(su));
    g_WoT[j*Cc + c] = __uint_as_float(tf32_of(so));
}

// ---------------------------------------------------------------------------
// k1: U = X_ @ W_u via tf32 MMA (R8 verbatim).
// ---------------------------------------------------------------------------
__global__ __launch_bounds__(256) void k1_u(const float* __restrict__ x) {
    extern __shared__ u32 sm1[];
    u32* xs = sm1;                 // 128*132
    u32* ws = sm1 + 128*132;       // 128*72
    int base = blockIdx.x * 128;
    int bt = base >> 11;
    int s0 = base & 2047;
    int b = bt >> 3, t = bt & 7;
    int tid = threadIdx.x;
    int wid = tid >> 5, lane = tid & 31, gid = lane >> 2, tig = lane & 3;
    int m0 = wid * 16;

    for (int idx = tid; idx < 4096; idx += 256) {
        int r = idx >> 5, c4 = idx & 31;
        float4 v = ((const float4*)(x + ((size_t)((b*Sc + s0 + r)*Tc + t))*Cc))[c4];
        uint4 u = make_uint4(tf32_of(v.x), tf32_of(v.y), tf32_of(v.z), tf32_of(v.w));
        *((uint4*)&xs[r*132 + c4*4]) = u;
    }
    __syncthreads();

    int rowA0 = (m0 + gid) * 132;
    int rowA1 = (m0 + gid + 8) * 132;

    for (int ch = 0; ch < 9; ch++) {
        int j0 = ch * 64;
        int jtn = (ch < 8) ? 8 : 2;
        int jw4 = jtn * 2;
        if (ch) __syncthreads();
        for (int idx = tid; idx < 128*jw4; idx += 256) {
            int c = idx / jw4, q = idx - c*jw4;
            uint4 w = ((const uint4*)(g_Wu + (size_t)c*UP + j0))[q];
            *((uint4*)&ws[c*72 + q*4]) = w;
        }
        __syncthreads();

        float acc[8][4];
        #pragma unroll
        for (int jt = 0; jt < 8; jt++)
            #pragma unroll
            for (int e = 0; e < 4; e++) acc[jt][e] = 0.f;

        #pragma unroll
        for (int ks = 0; ks < 16; ks++) {
            int kk = ks * 8;
            u32 a0 = xs[rowA0 + kk + tig];
            u32 a1 = xs[rowA1 + kk + tig];
            u32 a2 = xs[rowA0 + kk + tig + 4];
            u32 a3 = xs[rowA1 + kk + tig + 4];
            const u32* w0p = &ws[(kk + tig)*72 + gid];
            const u32* w1p = &ws[(kk + tig + 4)*72 + gid];
            #pragma unroll
            for (int jt = 0; jt < 8; jt++) {
                if (jt < jtn) {
                    mma_tf32(acc[jt], a0, a1, a2, a3, w0p[jt*8], w1p[jt*8]);
                }
            }
        }
        #pragma unroll
        for (int jt = 0; jt < 8; jt++) {
            if (jt < jtn) {
                int j = j0 + jt*8 + 2*tig;
                *((float2*)(g_U + (size_t)(base + m0 + gid    )*UP + j)) =
                    make_float2(acc[jt][0], acc[jt][1]);
                *((float2*)(g_U + (size_t)(base + m0 + gid + 8)*UP + j)) =
                    make_float2(acc[jt][2], acc[jt][3]);
            }
        }
    }
}

// ---------------------------------------------------------------------------
// k2: warp-autonomous attention (R11 winner, exact).
// ---------------------------------------------------------------------------
__global__ __launch_bounds__(128, 5) void k2_attn(const float* __restrict__ x,
                                                  const void* __restrict__ sidx,
                                                  const float* __restrict__ swgt,
                                                  const float* __restrict__ ali,
                                                  const float* __restrict__ dstp) {
    __shared__ __align__(16) float nb[4][Kc][NBS];     // 35.8 KB
    __shared__ __align__(16) float attn_s[4][Kc][4];   // [k][h] fp32
    __shared__ float logw[4][Kc];

    int tid = threadIdx.x;
    int n4 = tid >> 5, lane = tid & 31;
    int n = blockIdx.x * 4 + n4;
    int bt = n >> 11;
    int b = bt >> 3, t = bt & 7;
    int k = lane & 15, half = lane >> 4;
    int gid = lane >> 2, tig = lane & 3;

    // ---- P0: neighbor index (one per k, lanes 0-15 authoritative) ----
    int myjn;
    if (g_is64) myjn = (int)((const long long*)sidx)[(size_t)n*Kc + k];
    else        myjn = ((const int*)sidx)[(size_t)n*Kc + k];

    // coalesced gather: kg = lane>>3 (4 rows per pass), l8 = lane&7
    {
        int kg = lane >> 3, l8 = lane & 7;
        size_t xbase = ((size_t)(b*Sc))*Tc*Cc + (size_t)t*Cc;
        #pragma unroll
        for (int set = 0; set < 4; set++) {
            int kk = set*4 + kg;
            int jn_kk = __shfl_sync(0xffffffffu, myjn, kk);
            const float4* srck = (const float4*)(x + xbase + (size_t)jn_kk*Tc*Cc);
            #pragma unroll
            for (int q = 0; q < 4; q++) {
                int f4 = l8 + 8*q;
                *((float4*)&nb[n4][kk][f4*4]) = srck[f4];
            }
        }
    }
    if (half == 0) {
        nb[n4][k][128] = ali [(size_t)n*Kc + k];
        nb[n4][k][129] = dstp[(size_t)n*Kc + k];
    } else {
        #pragma unroll
        for (int e = 0; e < 6; e++) nb[n4][k][130 + e] = 0.f;  // zero MMA pad
    }
    if (lane < Kc)
        logw[n4][lane] = __logf(swgt[(size_t)n*Kc + lane] + 1e-6f);
    __syncwarp();

    // ---- P1: logits via 17 m16n8k8 tf32 MMAs; B direct from g_U ----
    float d[4] = {0.f, 0.f, 0.f, 0.f};
    {
        const float* nbr0 = &nb[n4][gid    ][0];
        const float* nbr1 = &nb[n4][gid + 8][0];
        const float* Urow = g_U + (size_t)n*UP + gid*Fc;   // only gid<4 read
        bool hv = (gid < 4);
        #pragma unroll
        for (int ks = 0; ks < 17; ks++) {
            int kk = ks * 8;
            u32 a0 = tf32_of(nbr0[kk + tig]);
            u32 a1 = tf32_of(nbr1[kk + tig]);
            u32 a2 = tf32_of(nbr0[kk + tig + 4]);
            u32 a3 = tf32_of(nbr1[kk + tig + 4]);
            int f0 = kk + tig, f1 = f0 + 4;
            u32 b0 = (hv && f0 < Fc) ? tf32_of(Urow[f0]) : 0u;
            u32 b1 = (hv && f1 < Fc) ? tf32_of(Urow[f1]) : 0u;
            mma_tf32(d, a0, a1, a2, a3, b0, b1);
        }
    }
    {
        float lw0 = logw[n4][gid];
        float lw1 = logw[n4][gid + 8];
        d[0] += lw0; d[1] += lw0;
        d[2] += lw1; d[3] += lw1;
    }

    // ---- P2: softmax over k (reduce over gid lanes: xor 4,8,16) ----
    {
        float m0 = fmaxf(d[0], d[2]);
        #pragma unroll
        for (int o = 4; o <= 16; o <<= 1)
            m0 = fmaxf(m0, __shfl_xor_sync(0xffffffffu, m0, o));
        float e0 = __expf(d[0] - m0), e2 = __expf(d[2] - m0);
        float s0 = e0 + e2;
        #pragma unroll
        for (int o = 4; o <= 16; o <<= 1)
            s0 += __shfl_xor_sync(0xffffffffu, s0, o);
        float a0 = e0 / s0, a2 = e2 / s0;

        float m1 = fmaxf(d[1], d[3]);
        #pragma unroll
        for (int o = 4; o <= 16; o <<= 1)
            m1 = fmaxf(m1, __shfl_xor_sync(0xffffffffu, m1, o));
        float e1 = __expf(d[1] - m1), e3 = __expf(d[3] - m1);
        float s1 = e1 + e3;
        #pragma unroll
        for (int o = 4; o <= 16; o <<= 1)
            s1 += __shfl_xor_sync(0xffffffffu, s1, o);
        float a1 = e1 / s1, a3 = e3 / s1;

        if (tig < 2) {   // heads 0..3 live in tig 0,1
            attn_s[n4][gid    ][2*tig    ] = a0;
            attn_s[n4][gid    ][2*tig + 1] = a1;
            attn_s[n4][gid + 8][2*tig    ] = a2;
            attn_s[n4][gid + 8][2*tig + 1] = a3;
        }
    }
    __syncwarp();

    // ---- P3: nbar; lane = f0, scalar fp32, attn via broadcast LDS.128 ----
    {
        float4 acc[4];
        float4 acc4t = make_float4(0.f,0.f,0.f,0.f);
        #pragma unroll
        for (int q = 0; q < 4; q++) acc[q] = make_float4(0.f,0.f,0.f,0.f);
        #pragma unroll
        for (int kk = 0; kk < Kc; kk++) {
            float4 a = *((const float4*)&attn_s[n4][kk][0]);
            const float* nbr = &nb[n4][kk][0];
            #pragma unroll
            for (int q = 0; q < 4; q++) {
                float v = nbr[lane + 32*q];
                acc[q].x = fmaf(a.x, v, acc[q].x);
                acc[q].y = fmaf(a.y, v, acc[q].y);
                acc[q].z = fmaf(a.z, v, acc[q].z);
                acc[q].w = fmaf(a.w, v, acc[q].w);
            }
            if (lane < 2) {
                float v = nbr[128 + lane];
                acc4t.x = fmaf(a.x, v, acc4t.x);
                acc4t.y = fmaf(a.y, v, acc4t.y);
                acc4t.z = fmaf(a.z, v, acc4t.z);
                acc4t.w = fmaf(a.w, v, acc4t.w);
            }
        }
        u32* dst = (u32*)(g_NB + (size_t)n*UP);
        #pragma unroll
        for (int q = 0; q < 4; q++) {
            int f = lane + 32*q;
            dst[0*Fc + f] = tf32_of(acc[q].x);
            dst[1*Fc + f] = tf32_of(acc[q].y);
            dst[2*Fc + f] = tf32_of(acc[q].z);
            dst[3*Fc + f] = tf32_of(acc[q].w);
        }
        if (lane < 2) {
            int f = 128 + lane;
            dst[0*Fc + f] = tf32_of(acc4t.x);
            dst[1*Fc + f] = tf32_of(acc4t.y);
            dst[2*Fc + f] = tf32_of(acc4t.z);
            dst[3*Fc + f] = tf32_of(acc4t.w);
        }
        if (lane < 8) dst[Uc + lane] = 0u;   // zero pad cols
    }
}

// ---------------------------------------------------------------------------
// k3: OUT = NB @ W_oT + bp via tf32 MMA, cp.async DOUBLE-BUFFERED pipeline.
// 128 rows/block (R11 tiling), k = 528 in 11 chunks of 48 (6 ks each).
// buf: NB 128x52 (26.6 KB) + WoT 48x136 (26.1 KB), x2 = 105.5 KB => 2 blk/SM.
// stage(ch+1) overlaps MMA(ch).
// ---------------------------------------------------------------------------
#define K3CH 48
#define K3NS 52        // NB buf row stride (52 % 32 == 20, conflict-free)
#define K3BUF (128*K3NS + K3CH*136)   // 13184 words per buffer

__global__ __launch_bounds__(256) void k3_out(const float* __restrict__ bp,
                                              float* __restrict__ out) {
    extern __shared__ u32 sm3[];
    int base = blockIdx.x * 128;
    int bt = base >> 11;
    int s0 = base & 2047;
    int b = bt >> 3, t = bt & 7;
    int tid = threadIdx.x;
    int wid = tid >> 5, lane = tid & 31, gid = lane >> 2, tig = lane & 3;
    int m0 = wid * 16;

    u32 smbase = smem_u32(sm3);

    // stage chunk ch into buffer bi via cp.async (12 x 16B per thread)
    auto stage = [&](int ch, int bi) {
        u32 nbuf = smbase + (u32)(bi*K3BUF)*4;
        u32 wbuf = nbuf + (u32)(128*K3NS)*4;
        int j0 = ch * K3CH;
        // NB: 128 rows x 12 uint4
        #pragma unroll
        for (int it = 0; it < 6; it++) {
            int idx = tid + it*256;
            int r = idx / 12, q = idx - r*12;
            cp16(nbuf + (u32)(r*K3NS + q*4)*4,
                 (const void*)(g_NB + (size_t)(base + r)*UP + j0 + q*4));
        }
        // WoT: 48 rows x 32 uint4
        #pragma unroll
        for (int it = 0; it < 6; it++) {
            int idx = tid + it*256;
            int kk = idx >> 5, q = idx & 31;
            cp16(wbuf + (u32)(kk*136 + q*4)*4,
                 (const void*)(g_WoT + (size_t)(j0 + kk)*Cc + q*4));
        }
        asm volatile("cp.async.commit_group;" ::: "memory");
    };

    float acc[16][4];
    #pragma unroll
    for (int jt = 0; jt < 16; jt++)
        #pragma unroll
        for (int e = 0; e < 4; e++) acc[jt][e] = 0.f;

    stage(0, 0);

    for (int ch = 0; ch < 11; ch++) {
        int bi = ch & 1;
        if (ch < 10) {
            stage(ch + 1, bi ^ 1);
            asm volatile("cp.async.wait_group 1;" ::: "memory");
        } else {
            asm volatile("cp.async.wait_group 0;" ::: "memory");
        }
        __syncthreads();   // chunk ch's fills visible to all warps

        const u32* nbuf = sm3 + bi*K3BUF;
        const u32* wbuf = nbuf + 128*K3NS;
        int rowA0 = (m0 + gid) * K3NS;
        int rowA1 = (m0 + gid + 8) * K3NS;

        #pragma unroll
        for (int ks = 0; ks < 6; ks++) {
            int kk = ks * 8;
            u32 a0 = nbuf[rowA0 + kk + tig];
            u32 a1 = nbuf[rowA1 + kk + tig];
            u32 a2 = nbuf[rowA0 + kk + tig + 4];
            u32 a3 = nbuf[rowA1 + kk + tig + 4];
            const u32* w0p = &wbuf[(kk + tig)*136 + gid];
            const u32* w1p = &wbuf[(kk + tig + 4)*136 + gid];
            #pragma unroll
            for (int jt = 0; jt < 16; jt++)
                mma_tf32(acc[jt], a0, a1, a2, a3, w0p[jt*8], w1p[jt*8]);
        }
        __syncthreads();   // buffer bi free before it's refilled at ch+2
    }

    #pragma unroll
    for (int jt = 0; jt < 16; jt++) {
        int cp = jt*8 + 2*tig;
        float2 bv = *((const float2*)&bp[cp]);
        int sA = s0 + m0 + gid;
        int sB = sA + 8;
        *((float2*)(out + ((size_t)((b*Sc + sA)*Tc + t))*Cc + cp)) =
            make_float2(acc[jt][0] + bv.x, acc[jt][1] + bv.y);
        *((float2*)(out + ((size_t)((b*Sc + sB)*Tc + t))*Cc + cp)) =
            make_float2(acc[jt][2] + bv.x, acc[jt][3] + bv.y);
    }
}

// ---------------------------------------------------------------------------
extern "C" void kernel_launch(void* const* d_in, const int* in_sizes, int n_in,
                              void* d_out, int out_size) {
    const float* x    = (const float*)d_in[0];
    const void*  sidx = d_in[1];
    const float* swgt = (const float*)d_in[2];
    const float* ali  = (const float*)d_in[3];
    const float* dstp = (const float*)d_in[4];
    const float* Wq   = (const float*)d_in[5];
    const float* Wk   = (const float*)d_in[6];
    const float* Wv   = (const float*)d_in[7];
    const float* Wp   = (const float*)d_in[8];
    const float* bp   = (const float*)d_in[9];
    float* out = (float*)d_out;

    const int SM1 = (128*132 + 128*72) * 4;
    const int SM3 = 2 * K3BUF * 4;           // 105,472 B
    cudaFuncSetAttribute(k1_u,   cudaFuncAttributeMaxDynamicSharedMemorySize, SM1);
    cudaFuncSetAttribute(k3_out, cudaFuncAttributeMaxDynamicSharedMemorySize, SM3);

    k0_combine<<<(Cc*UP + 255)/256, 256>>>(Wq, Wk, Wv, Wp,
                                           (const unsigned int*)sidx);
    k1_u<<<Nc/128, 256, SM1>>>(x);
    k2_attn<<<Nc/4, 128>>>(x, sidx, swgt, ali, dstp);
    k3_out<<<Nc/128, 256, SM3>>>(bp, out);
}

// round 17
// speedup vs baseline: 1.2156x; 1.0114x over previous
#include <cuda_runtime.h>
#include <math.h>

#define Bc 2
#define Sc 2048
#define Tc 8
#define Cc 128
#define Kc 16
#define Hc 4
#define Fc 130        // C+2
#define Nc 32768
#define Uc 520        // H*(C+2)
#define UP 528        // padded row stride for U/NB
#define NBS 140       // nb row stride (conflict-free for frag loads)

typedef unsigned int u32;

// ---- scratch (__device__ globals; no allocations allowed) ----
__device__ float g_Wu[Cc*UP];             // [c][j] tf32 bits, pad j>=520 zero
__device__ float g_WoT[UP*Cc];            // [j][c'] tf32 bits, pad rows zero
__device__ float g_U[(size_t)Nc*UP];      // fp32
__device__ float g_NB[(size_t)Nc*UP];     // tf32 bits (written by k2)
__device__ int   g_is64;

__device__ __forceinline__ u32 tf32_of(float f) {
    u32 u;
    asm("cvt.rna.tf32.f32 %0, %1;" : "=r"(u) : "f"(f));
    return u;
}
__device__ __forceinline__ void mma_tf32(float* d, u32 a0, u32 a1, u32 a2, u32 a3,
                                         u32 b0, u32 b1) {
    asm("mma.sync.aligned.m16n8k8.row.col.f32.tf32.tf32.f32 "
        "{%0,%1,%2,%3}, {%4,%5,%6,%7}, {%8,%9}, {%0,%1,%2,%3};"
        : "+f"(d[0]), "+f"(d[1]), "+f"(d[2]), "+f"(d[3])
        : "r"(a0), "r"(a1), "r"(a2), "r"(a3), "r"(b0), "r"(b1));
}
__device__ __forceinline__ u32 smem_u32(const void* p) {
    u32 a;
    asm("{ .reg .u64 t; cvta.to.shared.u64 t, %1; cvt.u32.u64 %0, t; }"
        : "=r"(a) : "l"(p));
    return a;
}
__device__ __forceinline__ void cp16(u32 dst, const void* src) {
    asm volatile("cp.async.cg.shared.global [%0], [%1], 16;" :: "r"(dst), "l"(src));
}

// ---------------------------------------------------------------------------
// k0: combined weights (tf32, zero-padded) + int32/int64 index sniff (block 0).
// ---------------------------------------------------------------------------
__global__ void k0_combine(const float* __restrict__ Wq, const float* __restrict__ Wk,
                           const float* __restrict__ Wv, const float* __restrict__ Wp,
                           const unsigned int* __restrict__ sp) {
    __shared__ int any;
    if (blockIdx.x == 0) {
        if (threadIdx.x == 0) any = 0;
        __syncthreads();
        for (int i = threadIdx.x; i < 4096; i += blockDim.x)
            if (sp[2*i + 1] != 0u) any = 1;
        __syncthreads();
        if (threadIdx.x == 0) g_is64 = (any == 0) ? 1 : 0;
    }

    int i = blockIdx.x * blockDim.x + threadIdx.x;
    if (i >= Cc*UP) return;
    int c = i / UP;
    int j = i % UP;
    float su = 0.f, so = 0.f;
    if (j < Uc) {
        int h = j / Fc;
        int f = j % Fc;
        #pragma unroll
        for (int d = 0; d < 32; d++) {
            int hd = h*32 + d;
            su = fmaf(Wq[hd*Cc + c], Wk[hd*(Cc+2) + f], su);
            so = fmaf(Wp[c*Cc + hd], Wv[hd*(Cc+2) + f], so);
        }
        su *= rsqrtf(32.f);
    }
    g_Wu[c*UP + j]  = __uint_as_float(tf32_of(su));
    g_WoT[j*Cc + c] = __uint_as_float(tf32_of(so));
}

// ---------------------------------------------------------------------------
// k1: U = X_ @ W_u via tf32 MMA, cp.async DOUBLE-BUFFERED over j-chunks.
// 128 rows/block; 17 chunks of 32 cols (last 16). ws stride 40 (conflict-free).
// smem = xs 67.6 KB + 2 x 20.5 KB = 108.5 KB => 2 blocks/SM.
// ---------------------------------------------------------------------------
#define K1CH 32
#define K1WS 40
#define K1WBUF (128*K1WS)    // 5120 words per buffer

__global__ __launch_bounds__(256) void k1_u(const float* __restrict__ x) {
    extern __shared__ u32 sm1[];
    u32* xs = sm1;                         // 128*132 = 16896 words
    u32* wb = sm1 + 128*132;               // 2 x K1WBUF
    int base = blockIdx.x * 128;
    int bt = base >> 11;
    int s0 = base & 2047;
    int b = bt >> 3, t = bt & 7;
    int tid = threadIdx.x;
    int wid = tid >> 5, lane = tid & 31, gid = lane >> 2, tig = lane & 3;
    int m0 = wid * 16;

    u32 smb = smem_u32(sm1);
    u32 wbase = smb + (u32)(128*132)*4;

    // stage x tile (tf32-converted) — registers path, overlaps first cp.async
    for (int idx = tid; idx < 4096; idx += 256) {
        int r = idx >> 5, c4 = idx & 31;
        float4 v = ((const float4*)(x + ((size_t)((b*Sc + s0 + r)*Tc + t))*Cc))[c4];
        uint4 u = make_uint4(tf32_of(v.x), tf32_of(v.y), tf32_of(v.z), tf32_of(v.w));
        *((uint4*)&xs[r*132 + c4*4]) = u;
    }

    // stage Wu chunk ch into buffer bi (cp.async; qn uint4 per k-row)
    auto stage = [&](int ch, int bi) {
        u32 buf = wbase + (u32)(bi*K1WBUF)*4;
        int j0 = ch * K1CH;
        int qn = (ch < 16) ? 8 : 4;
        for (int idx = tid; idx < 128*qn; idx += 256) {
            int c = idx / qn, q = idx - c*qn;
            cp16(buf + (u32)(c*K1WS + q*4)*4,
                 (const void*)(g_Wu + (size_t)c*UP + j0 + q*4));
        }
        asm volatile("cp.async.commit_group;" ::: "memory");
    };

    stage(0, 0);

    int rowA0 = (m0 + gid) * 132;
    int rowA1 = (m0 + gid + 8) * 132;

    for (int ch = 0; ch < 17; ch++) {
        int bi = ch & 1;
        if (ch < 16) {
            stage(ch + 1, bi ^ 1);
            asm volatile("cp.async.wait_group 1;" ::: "memory");
        } else {
            asm volatile("cp.async.wait_group 0;" ::: "memory");
        }
        __syncthreads();   // chunk ch fills + (ch==0) xs stage visible

        const u32* ws = wb + bi*K1WBUF;
        int jtn = (ch < 16) ? 4 : 2;

        float acc[4][4];
        #pragma unroll
        for (int jt = 0; jt < 4; jt++)
            #pragma unroll
            for (int e = 0; e < 4; e++) acc[jt][e] = 0.f;

        #pragma unroll
        for (int ks = 0; ks < 16; ks++) {
            int kk = ks * 8;
            u32 a0 = xs[rowA0 + kk + tig];
            u32 a1 = xs[rowA1 + kk + tig];
            u32 a2 = xs[rowA0 + kk + tig + 4];
            u32 a3 = xs[rowA1 + kk + tig + 4];
            const u32* w0p = &ws[(kk + tig)*K1WS + gid];
            const u32* w1p = &ws[(kk + tig + 4)*K1WS + gid];
            #pragma unroll
            for (int jt = 0; jt < 4; jt++) {
                if (jt < jtn)
                    mma_tf32(acc[jt], a0, a1, a2, a3, w0p[jt*8], w1p[jt*8]);
            }
        }
        #pragma unroll
        for (int jt = 0; jt < 4; jt++) {
            if (jt < jtn) {
                int j = ch*K1CH + jt*8 + 2*tig;
                *((float2*)(g_U + (size_t)(base + m0 + gid    )*UP + j)) =
                    make_float2(acc[jt][0], acc[jt][1]);
                *((float2*)(g_U + (size_t)(base + m0 + gid + 8)*UP + j)) =
                    make_float2(acc[jt][2], acc[jt][3]);
            }
        }
        __syncthreads();   // buffer bi free before refill at ch+2
    }
}

// ---------------------------------------------------------------------------
// k2: warp-autonomous attention (R11 winner, exact).
// ---------------------------------------------------------------------------
__global__ __launch_bounds__(128, 5) void k2_attn(const float* __restrict__ x,
                                                  const void* __restrict__ sidx,
                                                  const float* __restrict__ swgt,
                                                  const float* __restrict__ ali,
                                                  const float* __restrict__ dstp) {
    __shared__ __align__(16) float nb[4][Kc][NBS];     // 35.8 KB
    __shared__ __align__(16) float attn_s[4][Kc][4];   // [k][h] fp32
    __shared__ float logw[4][Kc];

    int tid = threadIdx.x;
    int n4 = tid >> 5, lane = tid & 31;
    int n = blockIdx.x * 4 + n4;
    int bt = n >> 11;
    int b = bt >> 3, t = bt & 7;
    int k = lane & 15, half = lane >> 4;
    int gid = lane >> 2, tig = lane & 3;

    // ---- P0: neighbor index (one per k, lanes 0-15 authoritative) ----
    int myjn;
    if (g_is64) myjn = (int)((const long long*)sidx)[(size_t)n*Kc + k];
    else        myjn = ((const int*)sidx)[(size_t)n*Kc + k];

    // coalesced gather: kg = lane>>3 (4 rows per pass), l8 = lane&7
    {
        int kg = lane >> 3, l8 = lane & 7;
        size_t xbase = ((size_t)(b*Sc))*Tc*Cc + (size_t)t*Cc;
        #pragma unroll
        for (int set = 0; set < 4; set++) {
            int kk = set*4 + kg;
            int jn_kk = __shfl_sync(0xffffffffu, myjn, kk);
            const float4* srck = (const float4*)(x + xbase + (size_t)jn_kk*Tc*Cc);
            #pragma unroll
            for (int q = 0; q < 4; q++) {
                int f4 = l8 + 8*q;
                *((float4*)&nb[n4][kk][f4*4]) = srck[f4];
            }
        }
    }
    if (half == 0) {
        nb[n4][k][128] = ali [(size_t)n*Kc + k];
        nb[n4][k][129] = dstp[(size_t)n*Kc + k];
    } else {
        #pragma unroll
        for (int e = 0; e < 6; e++) nb[n4][k][130 + e] = 0.f;  // zero MMA pad
    }
    if (lane < Kc)
        logw[n4][lane] = __logf(swgt[(size_t)n*Kc + lane] + 1e-6f);
    __syncwarp();

    // ---- P1: logits via 17 m16n8k8 tf32 MMAs; B direct from g_U ----
    float d[4] = {0.f, 0.f, 0.f, 0.f};
    {
        const float* nbr0 = &nb[n4][gid    ][0];
        const float* nbr1 = &nb[n4][gid + 8][0];
        const float* Urow = g_U + (size_t)n*UP + gid*Fc;   // only gid<4 read
        bool hv = (gid < 4);
        #pragma unroll
        for (int ks = 0; ks < 17; ks++) {
            int kk = ks * 8;
            u32 a0 = tf32_of(nbr0[kk + tig]);
            u32 a1 = tf32_of(nbr1[kk + tig]);
            u32 a2 = tf32_of(nbr0[kk + tig + 4]);
            u32 a3 = tf32_of(nbr1[kk + tig + 4]);
            int f0 = kk + tig, f1 = f0 + 4;
            u32 b0 = (hv && f0 < Fc) ? tf32_of(Urow[f0]) : 0u;
            u32 b1 = (hv && f1 < Fc) ? tf32_of(Urow[f1]) : 0u;
            mma_tf32(d, a0, a1, a2, a3, b0, b1);
        }
    }
    {
        float lw0 = logw[n4][gid];
        float lw1 = logw[n4][gid + 8];
        d[0] += lw0; d[1] += lw0;
        d[2] += lw1; d[3] += lw1;
    }

    // ---- P2: softmax over k (reduce over gid lanes: xor 4,8,16) ----
    {
        float m0 = fmaxf(d[0], d[2]);
        #pragma unroll
        for (int o = 4; o <= 16; o <<= 1)
            m0 = fmaxf(m0, __shfl_xor_sync(0xffffffffu, m0, o));
        float e0 = __expf(d[0] - m0), e2 = __expf(d[2] - m0);
        float s0 = e0 + e2;
        #pragma unroll
        for (int o = 4; o <= 16; o <<= 1)
            s0 += __shfl_xor_sync(0xffffffffu, s0, o);
        float a0 = e0 / s0, a2 = e2 / s0;

        float m1 = fmaxf(d[1], d[3]);
        #pragma unroll
        for (int o = 4; o <= 16; o <<= 1)
            m1 = fmaxf(m1, __shfl_xor_sync(0xffffffffu, m1, o));
        float e1 = __expf(d[1] - m1), e3 = __expf(d[3] - m1);
        float s1 = e1 + e3;
        #pragma unroll
        for (int o = 4; o <= 16; o <<= 1)
            s1 += __shfl_xor_sync(0xffffffffu, s1, o);
        float a1 = e1 / s1, a3 = e3 / s1;

        if (tig < 2) {   // heads 0..3 live in tig 0,1
            attn_s[n4][gid    ][2*tig    ] = a0;
            attn_s[n4][gid    ][2*tig + 1] = a1;
            attn_s[n4][gid + 8][2*tig    ] = a2;
            attn_s[n4][gid + 8][2*tig + 1] = a3;
        }
    }
    __syncwarp();

    // ---- P3: nbar; lane = f0, scalar fp32, attn via broadcast LDS.128 ----
    {
        float4 acc[4];
        float4 acc4t = make_float4(0.f,0.f,0.f,0.f);
        #pragma unroll
        for (int q = 0; q < 4; q++) acc[q] = make_float4(0.f,0.f,0.f,0.f);
        #pragma unroll
        for (int kk = 0; kk < Kc; kk++) {
            float4 a = *((const float4*)&attn_s[n4][kk][0]);
            const float* nbr = &nb[n4][kk][0];
            #pragma unroll
            for (int q = 0; q < 4; q++) {
                float v = nbr[lane + 32*q];
                acc[q].x = fmaf(a.x, v, acc[q].x);
                acc[q].y = fmaf(a.y, v, acc[q].y);
                acc[q].z = fmaf(a.z, v, acc[q].z);
                acc[q].w = fmaf(a.w, v, acc[q].w);
            }
            if (lane < 2) {
                float v = nbr[128 + lane];
                acc4t.x = fmaf(a.x, v, acc4t.x);
                acc4t.y = fmaf(a.y, v, acc4t.y);
                acc4t.z = fmaf(a.z, v, acc4t.z);
                acc4t.w = fmaf(a.w, v, acc4t.w);
            }
        }
        u32* dst = (u32*)(g_NB + (size_t)n*UP);
        #pragma unroll
        for (int q = 0; q < 4; q++) {
            int f = lane + 32*q;
            dst[0*Fc + f] = tf32_of(acc[q].x);
            dst[1*Fc + f] = tf32_of(acc[q].y);
            dst[2*Fc + f] = tf32_of(acc[q].z);
            dst[3*Fc + f] = tf32_of(acc[q].w);
        }
        if (lane < 2) {
            int f = 128 + lane;
            dst[0*Fc + f] = tf32_of(acc4t.x);
            dst[1*Fc + f] = tf32_of(acc4t.y);
            dst[2*Fc + f] = tf32_of(acc4t.z);
            dst[3*Fc + f] = tf32_of(acc4t.w);
        }
        if (lane < 8) dst[Uc + lane] = 0u;   // zero pad cols
    }
}

// ---------------------------------------------------------------------------
// k3: OUT = NB @ W_oT + bp via tf32 MMA, cp.async double-buffered (R16 winner).
// ---------------------------------------------------------------------------
#define K3CH 48
#define K3NS 52
#define K3BUF (128*K3NS + K3CH*136)   // 13184 words per buffer

__global__ __launch_bounds__(256) void k3_out(const float* __restrict__ bp,
                                              float* __restrict__ out) {
    extern __shared__ u32 sm3[];
    int base = blockIdx.x * 128;
    int bt = base >> 11;
    int s0 = base & 2047;
    int b = bt >> 3, t = bt & 7;
    int tid = threadIdx.x;
    int wid = tid >> 5, lane = tid & 31, gid = lane >> 2, tig = lane & 3;
    int m0 = wid * 16;

    u32 smbase = smem_u32(sm3);

    auto stage = [&](int ch, int bi) {
        u32 nbuf = smbase + (u32)(bi*K3BUF)*4;
        u32 wbuf = nbuf + (u32)(128*K3NS)*4;
        int j0 = ch * K3CH;
        #pragma unroll
        for (int it = 0; it < 6; it++) {
            int idx = tid + it*256;
            int r = idx / 12, q = idx - r*12;
            cp16(nbuf + (u32)(r*K3NS + q*4)*4,
                 (const void*)(g_NB + (size_t)(base + r)*UP + j0 + q*4));
        }
        #pragma unroll
        for (int it = 0; it < 6; it++) {
            int idx = tid + it*256;
            int kk = idx >> 5, q = idx & 31;
            cp16(wbuf + (u32)(kk*136 + q*4)*4,
                 (const void*)(g_WoT + (size_t)(j0 + kk)*Cc + q*4));
        }
        asm volatile("cp.async.commit_group;" ::: "memory");
    };

    float acc[16][4];
    #pragma unroll
    for (int jt = 0; jt < 16; jt++)
        #pragma unroll
        for (int e = 0; e < 4; e++) acc[jt][e] = 0.f;

    stage(0, 0);

    for (int ch = 0; ch < 11; ch++) {
        int bi = ch & 1;
        if (ch < 10) {
            stage(ch + 1, bi ^ 1);
            asm volatile("cp.async.wait_group 1;" ::: "memory");
        } else {
            asm volatile("cp.async.wait_group 0;" ::: "memory");
        }
        __syncthreads();

        const u32* nbuf = sm3 + bi*K3BUF;
        const u32* wbuf = nbuf + 128*K3NS;
        int rowA0 = (m0 + gid) * K3NS;
        int rowA1 = (m0 + gid + 8) * K3NS;

        #pragma unroll
        for (int ks = 0; ks < 6; ks++) {
            int kk = ks * 8;
            u32 a0 = nbuf[rowA0 + kk + tig];
            u32 a1 = nbuf[rowA1 + kk + tig];
            u32 a2 = nbuf[rowA0 + kk + tig + 4];
            u32 a3 = nbuf[rowA1 + kk + tig + 4];
            const u32* w0p = &wbuf[(kk + tig)*136 + gid];
            const u32* w1p = &wbuf[(kk + tig + 4)*136 + gid];
            #pragma unroll
            for (int jt = 0; jt < 16; jt++)
                mma_tf32(acc[jt], a0, a1, a2, a3, w0p[jt*8], w1p[jt*8]);
        }
        __syncthreads();
    }

    #pragma unroll
    for (int jt = 0; jt < 16; jt++) {
        int cp = jt*8 + 2*tig;
        float2 bv = *((const float2*)&bp[cp]);
        int sA = s0 + m0 + gid;
        int sB = sA + 8;
        *((float2*)(out + ((size_t)((b*Sc + sA)*Tc + t))*Cc + cp)) =
            make_float2(acc[jt][0] + bv.x, acc[jt][1] + bv.y);
        *((float2*)(out + ((size_t)((b*Sc + sB)*Tc + t))*Cc + cp)) =
            make_float2(acc[jt][2] + bv.x, acc[jt][3] + bv.y);
    }
}

// ---------------------------------------------------------------------------
extern "C" void kernel_launch(void* const* d_in, const int* in_sizes, int n_in,
                              void* d_out, int out_size) {
    const float* x    = (const float*)d_in[0];
    const void*  sidx = d_in[1];
    const float* swgt = (const float*)d_in[2];
    const float* ali  = (const float*)d_in[3];
    const float* dstp = (const float*)d_in[4];
    const float* Wq   = (const float*)d_in[5];
    const float* Wk   = (const float*)d_in[6];
    const float* Wv   = (const float*)d_in[7];
    const float* Wp   = (const float*)d_in[8];
    const float* bp   = (const float*)d_in[9];
    float* out = (float*)d_out;

    const int SM1 = (128*132 + 2*K1WBUF) * 4;   // 108,544 B
    const int SM3 = 2 * K3BUF * 4;              // 105,472 B
    cudaFuncSetAttribute(k1_u,   cudaFuncAttributeMaxDynamicSharedMemorySize, SM1);
    cudaFuncSetAttribute(k3_out, cudaFuncAttributeMaxDynamicSharedMemorySize, SM3);

    k0_combine<<<(Cc*UP + 255)/256, 256>>>(Wq, Wk, Wv, Wp,
                                           (const unsigned int*)sidx);
    k1_u<<<Nc/128, 256, SM1>>>(x);
    k2_attn<<<Nc/4, 128>>>(x, sidx, swgt, ali, dstp);
    k3_out<<<Nc/128, 256, SM3>>>(bp, out);
}